// round 13
// baseline (speedup 1.0000x reference)
#include <cuda_runtime.h>
#include <cuda_bf16.h>
#include <cstdint>

// QSRGAN: x [256,256,5] f32, q_params [4,30] f32 -> out [4,512,512,16] f32.
//
// SINGLE kernel with block-0 producer handshake:
//  Block 0 (threads 0-127) evolves the 32 basis columns through the 6-layer
//  RY+CZ circuit for all 4 generators and emits W rows 0..15 as bf16 hi/lo
//  mma B-fragments to global g_Bfrag, then sets g_flag (release). All blocks
//  compute their pixel states FIRST (independent), then wait on g_flag
//  (block 0 is in wave 1 -> no deadlock), copy fragments to smem, and run
//  the MMA phase. A finish-counter resets g_flag/g_fin at the end of each
//  launch (state net-zero per launch -> graph-replay safe, deterministic).
//
//  Math: per warp = 32 pixels, two m16 tiles; [16x32]x[32x64] contraction via
//  mma.sync.m16n8k16 bf16 with 3-term hi/lo split AhiBhi+AloBhi+AhiBlo
//  (residual ~2^-17). Epilogue: square, quad-shuffle max, normalize.
//  (sum-normalization cancels: p/sum/max(p/sum) = p/max(p))
//
// Layouts:
//  B fragments (bf16): float4 idx (g*2+kt)*32+lane = {nt0_b0,nt0_b1,nt1_b0,
//    nt1_b1}; hi = first 256 float4, lo = next 256. INTERLEAVED columns:
//    gen col i -> ntile=(i>>1)&1, n_in_tile=2*(i>>2)+(i&1), so each lane's
//    4 outputs are contiguous cols 4q..4q+3 -> float4 epilogue stores.
//  State S2[k2][pixel] float2 pairs (k even, k odd), row stride 36 float2
//    -> conflict-free STS.64 stores and LDS.64 fragment reads.

#define DIM 32
#define KEEPN 16
#define NGEN 4
#define IW 256
#define NPIX (512*512)
#define ST2 36          // S2 row stride in float2 units

__device__ __align__(16) __nv_bfloat16 g_Bfrag[4096];   // hi[2048], lo[2048]
__device__ int g_flag = 0;
__device__ int g_fin  = 0;

// sin/cos of t in [0, 0.5] via Taylor (err < 1e-9)
__device__ __forceinline__ void poly_sincos(float t, float& s, float& c) {
    float t2 = t * t;
    s = t * (1.0f + t2 * (-1.0f / 6.0f + t2 * (1.0f / 120.0f)));
    c = 1.0f + t2 * (-0.5f + t2 * (1.0f / 24.0f + t2 * (-1.0f / 720.0f)));
}

// pack two floats into bf16x2: lower half = first arg
__device__ __forceinline__ uint32_t pack_bf16x2(float even, float odd) {
    uint32_t d;
    asm("cvt.rn.bf16x2.f32 %0, %1, %2;" : "=r"(d) : "f"(odd), "f"(even));
    return d;
}

#define MMA_BF16(C, A, B0, B1)                                                 \
    asm volatile("mma.sync.aligned.m16n8k16.row.col.f32.bf16.bf16.f32 "        \
                 "{%0,%1,%2,%3}, {%4,%5,%6,%7}, {%8,%9}, {%0,%1,%2,%3};"       \
                 : "+f"((C)[0]), "+f"((C)[1]), "+f"((C)[2]), "+f"((C)[3])      \
                 : "r"((A)[0]), "r"((A)[1]), "r"((A)[2]), "r"((A)[3]),         \
                   "r"(B0), "r"(B1))

__global__ void __launch_bounds__(256, 3) qsrgan_one_kernel(
    const float* __restrict__ x, const float* __restrict__ qp,
    float* __restrict__ out)
{
    extern __shared__ float smem[];
    float*  shB = smem;                                    // 2048 floats (8KB)
    float2* shS = reinterpret_cast<float2*>(smem + 2048);  // 8 warps * 16 * ST2

    const int tid  = threadIdx.x;
    const int lane = tid & 31;
    const int warp = tid >> 5;

    // ---------------- Phase A: W fragments (block 0, threads 0..127) -------
    if (blockIdx.x == 0 && tid < 128) {
        const int g = tid >> 5;        // generator
        const int j = tid & 31;        // basis column (= GEMM k index)

        float st[DIM];
#pragma unroll
        for (int i = 0; i < DIM; i++) st[i] = (i == j) ? 1.0f : 0.0f;

#pragma unroll 1
        for (int d = 0; d < 6; d++) {
#pragma unroll
            for (int q = 0; q < 5; q++) {
                float s, c;
                poly_sincos(0.5f * qp[g * 30 + d * 5 + q], s, c);
                const int r = 1 << (4 - q);
#pragma unroll
                for (int i = 0; i < DIM; i++) {
                    if ((i & r) == 0) {
                        float a0 = st[i];
                        float a1 = st[i | r];
                        st[i]     = c * a0 - s * a1;
                        st[i | r] = s * a0 + c * a1;
                    }
                }
            }
#pragma unroll
            for (int i = 0; i < DIM; i++) {
                if (__popc(i & (i >> 1)) & 1) st[i] = -st[i];
            }
        }

        // Emit fragments. B[k=j][gen col i] = st[i], interleaved columns.
        const int kt  = j >> 4;
        const int kk  = j & 15;
        const int r8  = kk >> 3;
        const int ck  = (kk >> 1) & 3;
        const int par = kk & 1;
#pragma unroll
        for (int i = 0; i < KEEPN; i++) {
            float v = st[i];
            __nv_bfloat16 hi = __float2bfloat16(v);
            __nv_bfloat16 lo = __float2bfloat16(v - __bfloat162float(hi));
            int nt   = (i >> 1) & 1;
            int jn   = 2 * (i >> 2) + (i & 1);
            int lane2 = 4 * jn + ck;
            int elem  = nt * 2 + r8;
            int idx   = (((g * 2 + kt) * 32 + lane2) * 4 + elem) * 2 + par;
            g_Bfrag[idx]        = hi;
            g_Bfrag[2048 + idx] = lo;
        }
    }

    // ---------------- Phase B: per-pixel state (all blocks, all threads) ---
    const int p  = blockIdx.x * 256 + tid;
    const int oy = p >> 9;
    const int ox = p & 511;

    float syf = oy * 0.5f - 0.25f;
    int   y0  = __float2int_rd(syf);
    float fy  = syf - (float)y0;
    int y0c = max(y0, 0);
    int y1c = min(y0 + 1, IW - 1);

    float sxf = ox * 0.5f - 0.25f;
    int   x0  = __float2int_rd(sxf);
    float fx  = sxf - (float)x0;
    int x0c = max(x0, 0);
    int x1c = min(x0 + 1, IW - 1);

    const float* p00 = x + (y0c * IW + x0c) * 5;
    const float* p01 = x + (y0c * IW + x1c) * 5;
    const float* p10 = x + (y1c * IW + x0c) * 5;
    const float* p11 = x + (y1c * IW + x1c) * 5;

    float cc[5], ss[5];
#pragma unroll
    for (int c = 0; c < 5; c++) {
        float v00 = __ldg(p00 + c);
        float v01 = __ldg(p01 + c);
        float v10 = __ldg(p10 + c);
        float v11 = __ldg(p11 + c);
        float top = v00 + fx * (v01 - v00);
        float bot = v10 + fx * (v11 - v10);
        float a   = top + fy * (bot - top);
        poly_sincos(0.5f * a, ss[c], cc[c]);     // a in [0,1) -> t in [0,0.5]
    }

    {
        float t01[4];
#pragma unroll
        for (int i = 0; i < 4; i++)
            t01[i] = ((i >> 1) ? ss[0] : cc[0]) * ((i & 1) ? ss[1] : cc[1]);
        float t012[8];
#pragma unroll
        for (int i = 0; i < 8; i++)
            t012[i] = t01[i >> 1] * ((i & 1) ? ss[2] : cc[2]);
        float t0123[16];
#pragma unroll
        for (int i = 0; i < 16; i++)
            t0123[i] = t012[i >> 1] * ((i & 1) ? ss[3] : cc[3]);

        float2* Sw2 = shS + warp * (16 * ST2) + lane;
        float c4 = cc[4], s4 = ss[4];
#pragma unroll
        for (int i = 0; i < 16; i++)
            Sw2[i * ST2] = make_float2(t0123[i] * c4, t0123[i] * s4);
    }

    // ---------------- Handshake: wait for W fragments ----------------------
    __syncthreads();                       // block 0: Phase A complete
    if (blockIdx.x == 0) {
        if (tid == 0) {
            __threadfence();
            atomicExch(&g_flag, 1);        // release
        }
    } else if (tid == 0) {
        while (atomicAdd(&g_flag, 0) == 0) __nanosleep(200);
        __threadfence();                   // acquire
    }
    __syncthreads();

    // cooperative copy of B fragments (8 KB = 512 float4)
    {
        const float4* src = reinterpret_cast<const float4*>(g_Bfrag);
        float4* dst = reinterpret_cast<float4*>(shB);
        dst[tid]       = src[tid];
        dst[tid + 256] = src[tid + 256];
    }
    __syncthreads();

    // ---------------- Phase C: MMA + epilogue ------------------------------
    const float2* Sw2 = shS + warp * (16 * ST2);
    const float4* Bhi4 = reinterpret_cast<const float4*>(shB);
    const float4* Blo4 = Bhi4 + 256;
    const int warpBase = blockIdx.x * 256 + warp * 32;
    const int qc4 = 4 * (lane & 3);

    // A fragments for BOTH m-tiles (bf16 hi/lo): [m][kt][reg] = 32 regs
    uint32_t ahi[2][2][4], alo[2][2][4];
    {
        const int c0 = lane & 3;
#pragma unroll
        for (int m = 0; m < 2; m++) {
            const int r0 = m * 16 + (lane >> 2);
#pragma unroll
            for (int kt = 0; kt < 2; kt++) {
#pragma unroll
                for (int rg = 0; rg < 4; rg++) {
                    int row = r0 + (rg & 1) * 8;
                    int k2  = c0 + 4 * (rg >> 1) + 8 * kt;
                    float2 f = Sw2[k2 * ST2 + row];
                    uint32_t h = pack_bf16x2(f.x, f.y);
                    float he = __uint_as_float(h << 16);
                    float ho = __uint_as_float(h & 0xffff0000u);
                    ahi[m][kt][rg] = h;
                    alo[m][kt][rg] = pack_bf16x2(f.x - he, f.y - ho);
                }
            }
        }
    }

#pragma unroll 1
    for (int g = 0; g < NGEN; g++) {
        float c[2][2][4];   // [m][ntile][reg]
#pragma unroll
        for (int m = 0; m < 2; m++)
#pragma unroll
            for (int nt = 0; nt < 2; nt++)
#pragma unroll
                for (int q = 0; q < 4; q++) c[m][nt][q] = 0.0f;

#pragma unroll
        for (int kt = 0; kt < 2; kt++) {
            const int bidx = (g * 2 + kt) * 32 + lane;
            float4 bh = Bhi4[bidx];   // {nt0_b0, nt0_b1, nt1_b0, nt1_b1}
            float4 bl = Blo4[bidx];
            uint32_t bh00 = __float_as_uint(bh.x), bh01 = __float_as_uint(bh.y);
            uint32_t bh10 = __float_as_uint(bh.z), bh11 = __float_as_uint(bh.w);
            uint32_t bl00 = __float_as_uint(bl.x), bl01 = __float_as_uint(bl.y);
            uint32_t bl10 = __float_as_uint(bl.z), bl11 = __float_as_uint(bl.w);
#pragma unroll
            for (int m = 0; m < 2; m++) {
                MMA_BF16(c[m][0], ahi[m][kt], bh00, bh01);
                MMA_BF16(c[m][1], ahi[m][kt], bh10, bh11);
                MMA_BF16(c[m][0], alo[m][kt], bh00, bh01);
                MMA_BF16(c[m][1], alo[m][kt], bh10, bh11);
                MMA_BF16(c[m][0], ahi[m][kt], bl00, bl01);
                MMA_BF16(c[m][1], ahi[m][kt], bl10, bl11);
            }
        }

        // epilogue: lane's 4 outputs are contiguous cols 4q..4q+3
#pragma unroll
        for (int m = 0; m < 2; m++) {
            const int rowA = warpBase + m * 16 + (lane >> 2);
            const int rowB = rowA + 8;

            float xa0 = c[m][0][0] * c[m][0][0];
            float xa1 = c[m][0][1] * c[m][0][1];
            float xa2 = c[m][1][0] * c[m][1][0];
            float xa3 = c[m][1][1] * c[m][1][1];
            float xb0 = c[m][0][2] * c[m][0][2];
            float xb1 = c[m][0][3] * c[m][0][3];
            float xb2 = c[m][1][2] * c[m][1][2];
            float xb3 = c[m][1][3] * c[m][1][3];

            float ma = fmaxf(fmaxf(xa0, xa1), fmaxf(xa2, xa3));
            float mb = fmaxf(fmaxf(xb0, xb1), fmaxf(xb2, xb3));
            ma = fmaxf(ma, __shfl_xor_sync(0xffffffffu, ma, 1));
            mb = fmaxf(mb, __shfl_xor_sync(0xffffffffu, mb, 1));
            ma = fmaxf(ma, __shfl_xor_sync(0xffffffffu, ma, 2));
            mb = fmaxf(mb, __shfl_xor_sync(0xffffffffu, mb, 2));
            float ia = __fdividef(1.0f, ma);
            float ib = __fdividef(1.0f, mb);

            float4 va = make_float4(xa0 * ia, xa1 * ia, xa2 * ia, xa3 * ia);
            float4 vb = make_float4(xb0 * ib, xb1 * ib, xb2 * ib, xb3 * ib);
            *reinterpret_cast<float4*>(
                out + ((size_t)g * NPIX + rowA) * KEEPN + qc4) = va;
            *reinterpret_cast<float4*>(
                out + ((size_t)g * NPIX + rowB) * KEEPN + qc4) = vb;
        }
    }

    // ---------------- self-reset for next launch / graph replay ------------
    __syncthreads();
    if (tid == 0) {
        int d = atomicAdd(&g_fin, 1);
        if (d == (int)gridDim.x - 1) {
            g_fin = 0;
            __threadfence();
            atomicExch(&g_flag, 0);
        }
    }
}

// ---------------------------------------------------------------------------
extern "C" void kernel_launch(void* const* d_in, const int* in_sizes, int n_in,
                              void* d_out, int out_size)
{
    const float* x  = (const float*)d_in[0];   // [256,256,5]
    const float* qp = (const float*)d_in[1];   // [4,30]
    float* out = (float*)d_out;                // [4,512,512,16]

    const int smem_bytes = 2048 * 4 + 8 * 16 * ST2 * 8;   // 8KB + 36KB = 45056
    cudaFuncSetAttribute(qsrgan_one_kernel,
                         cudaFuncAttributeMaxDynamicSharedMemorySize, smem_bytes);

    qsrgan_one_kernel<<<NPIX / 256, 256, smem_bytes>>>(x, qp, out);
}

// round 14
// speedup vs baseline: 1.1293x; 1.1293x over previous
#include <cuda_runtime.h>
#include <cuda_bf16.h>
#include <cstdint>

// QSRGAN: x [256,256,5] f32, q_params [4,30] f32 -> out [4,512,512,16] f32.
//
// Two kernels (R11 structure) + R12 codegen wins:
//  Kernel 1 (runs once, 1 block x 128 threads): evolve 32 basis columns
//    through the 6-layer RY+CZ circuit per generator; emit W rows 0..15 as
//    bf16 hi/lo mma B-fragments with INTERLEAVED column mapping.
//  Kernel 2: copy fragments to smem (8KB); per pixel bilinear upsample + poly
//    sincos; stage rank-1 product state as float2 pairs S2[k2][pixel]
//    (stride 36 float2 -> conflict-free STS.64 stores + LDS.64 reads).
//    Build BOTH m16 tiles' A hi/lo fragments up front; per generator load
//    each B hi/lo float4 pair exactly once; mma.sync.m16n8k16 bf16 with
//    3-term split AhiBhi+AloBhi+AhiBlo (residual ~2^-17).
//    Epilogue: square, quad-shuffle max, normalize; interleaved B columns
//    make each lane's 4 outputs contiguous -> float4 stores.
//  (sum-normalization cancels: p/sum/max(p/sum) = p/max(p))
//
// B fragment layout (bf16): float4 idx (g*2+kt)*32+lane = {nt0_b0,nt0_b1,
//   nt1_b0,nt1_b1}; hi = first 256 float4, lo = next 256.
//   Column interleave: gen col i -> ntile=(i>>1)&1, n_in_tile=2*(i>>2)+(i&1).

#define DIM 32
#define KEEPN 16
#define NGEN 4
#define IW 256
#define NPIX (512*512)
#define ST2 36          // S2 row stride in float2 units

__device__ __align__(16) __nv_bfloat16 g_Bfrag[4096];   // hi[2048], lo[2048]

// sin/cos of t in [0, 0.5] via Taylor (err < 1e-9)
__device__ __forceinline__ void poly_sincos(float t, float& s, float& c) {
    float t2 = t * t;
    s = t * (1.0f + t2 * (-1.0f / 6.0f + t2 * (1.0f / 120.0f)));
    c = 1.0f + t2 * (-0.5f + t2 * (1.0f / 24.0f + t2 * (-1.0f / 720.0f)));
}

// pack two floats into bf16x2: lower half = first arg
__device__ __forceinline__ uint32_t pack_bf16x2(float even, float odd) {
    uint32_t d;
    asm("cvt.rn.bf16x2.f32 %0, %1, %2;" : "=r"(d) : "f"(odd), "f"(even));
    return d;
}

#define MMA_BF16(C, A, B0, B1)                                                 \
    asm volatile("mma.sync.aligned.m16n8k16.row.col.f32.bf16.bf16.f32 "        \
                 "{%0,%1,%2,%3}, {%4,%5,%6,%7}, {%8,%9}, {%0,%1,%2,%3};"       \
                 : "+f"((C)[0]), "+f"((C)[1]), "+f"((C)[2]), "+f"((C)[3])      \
                 : "r"((A)[0]), "r"((A)[1]), "r"((A)[2]), "r"((A)[3]),         \
                   "r"(B0), "r"(B1))

// ---------------------------------------------------------------------------
// Kernel 1: precompute circuit matrix fragments (1 block x 128 threads)
// ---------------------------------------------------------------------------
__global__ void precompute_W_kernel(const float* __restrict__ qp)
{
    const int g = threadIdx.x >> 5;    // generator
    const int j = threadIdx.x & 31;    // basis column (= GEMM k index)

    float st[DIM];
#pragma unroll
    for (int i = 0; i < DIM; i++) st[i] = (i == j) ? 1.0f : 0.0f;

#pragma unroll 1
    for (int d = 0; d < 6; d++) {
#pragma unroll
        for (int q = 0; q < 5; q++) {
            float s, c;
            poly_sincos(0.5f * qp[g * 30 + d * 5 + q], s, c);
            const int r = 1 << (4 - q);
#pragma unroll
            for (int i = 0; i < DIM; i++) {
                if ((i & r) == 0) {
                    float a0 = st[i];
                    float a1 = st[i | r];
                    st[i]     = c * a0 - s * a1;
                    st[i | r] = s * a0 + c * a1;
                }
            }
        }
#pragma unroll
        for (int i = 0; i < DIM; i++) {
            if (__popc(i & (i >> 1)) & 1) st[i] = -st[i];
        }
    }

    // Emit fragments. B[k=j][gen col i] = st[i], interleaved columns.
    const int kt  = j >> 4;
    const int kk  = j & 15;
    const int r8  = kk >> 3;
    const int ck  = (kk >> 1) & 3;
    const int par = kk & 1;
#pragma unroll
    for (int i = 0; i < KEEPN; i++) {
        float v = st[i];
        __nv_bfloat16 hi = __float2bfloat16(v);
        __nv_bfloat16 lo = __float2bfloat16(v - __bfloat162float(hi));
        int nt    = (i >> 1) & 1;
        int jn    = 2 * (i >> 2) + (i & 1);
        int lane2 = 4 * jn + ck;
        int elem  = nt * 2 + r8;
        int idx   = (((g * 2 + kt) * 32 + lane2) * 4 + elem) * 2 + par;
        g_Bfrag[idx]        = hi;
        g_Bfrag[2048 + idx] = lo;
    }
}

// ---------------------------------------------------------------------------
// Kernel 2: main kernel. 1024 blocks x 256 threads, each warp = 32 pixels.
// ---------------------------------------------------------------------------
__global__ void __launch_bounds__(256, 3) qsrgan_mma_kernel(
    const float* __restrict__ x, float* __restrict__ out)
{
    extern __shared__ float smem[];
    float*  shB = smem;                                    // 2048 floats (8KB)
    float2* shS = reinterpret_cast<float2*>(smem + 2048);  // 8 warps * 16 * ST2

    const int tid  = threadIdx.x;
    const int lane = tid & 31;
    const int warp = tid >> 5;

    // cooperative copy of B fragments (8 KB = 512 float4)
    {
        const float4* src = reinterpret_cast<const float4*>(g_Bfrag);
        float4* dst = reinterpret_cast<float4*>(shB);
        dst[tid]       = src[tid];
        dst[tid + 256] = src[tid + 256];
    }

    // ---------------- Phase B: per-pixel state ----------------
    const int p  = blockIdx.x * 256 + tid;
    const int oy = p >> 9;
    const int ox = p & 511;

    float syf = oy * 0.5f - 0.25f;
    int   y0  = __float2int_rd(syf);
    float fy  = syf - (float)y0;
    int y0c = max(y0, 0);
    int y1c = min(y0 + 1, IW - 1);

    float sxf = ox * 0.5f - 0.25f;
    int   x0  = __float2int_rd(sxf);
    float fx  = sxf - (float)x0;
    int x0c = max(x0, 0);
    int x1c = min(x0 + 1, IW - 1);

    const float* p00 = x + (y0c * IW + x0c) * 5;
    const float* p01 = x + (y0c * IW + x1c) * 5;
    const float* p10 = x + (y1c * IW + x0c) * 5;
    const float* p11 = x + (y1c * IW + x1c) * 5;

    float cc[5], ss[5];
#pragma unroll
    for (int c = 0; c < 5; c++) {
        float v00 = __ldg(p00 + c);
        float v01 = __ldg(p01 + c);
        float v10 = __ldg(p10 + c);
        float v11 = __ldg(p11 + c);
        float top = v00 + fx * (v01 - v00);
        float bot = v10 + fx * (v11 - v10);
        float a   = top + fy * (bot - top);
        poly_sincos(0.5f * a, ss[c], cc[c]);     // a in [0,1) -> t in [0,0.5]
    }

    {
        float t01[4];
#pragma unroll
        for (int i = 0; i < 4; i++)
            t01[i] = ((i >> 1) ? ss[0] : cc[0]) * ((i & 1) ? ss[1] : cc[1]);
        float t012[8];
#pragma unroll
        for (int i = 0; i < 8; i++)
            t012[i] = t01[i >> 1] * ((i & 1) ? ss[2] : cc[2]);
        float t0123[16];
#pragma unroll
        for (int i = 0; i < 16; i++)
            t0123[i] = t012[i >> 1] * ((i & 1) ? ss[3] : cc[3]);

        float2* Sw2 = shS + warp * (16 * ST2) + lane;
        float c4 = cc[4], s4 = ss[4];
#pragma unroll
        for (int i = 0; i < 16; i++)
            Sw2[i * ST2] = make_float2(t0123[i] * c4, t0123[i] * s4);
    }
    __syncthreads();   // B fragments + all states visible

    // ---------------- Phase C: MMA + epilogue ------------------------------
    const float2* Sw2 = shS + warp * (16 * ST2);
    const float4* Bhi4 = reinterpret_cast<const float4*>(shB);
    const float4* Blo4 = Bhi4 + 256;
    const int warpBase = blockIdx.x * 256 + warp * 32;
    const int qc4 = 4 * (lane & 3);

    // A fragments for BOTH m-tiles (bf16 hi/lo): [m][kt][reg] = 32 regs
    uint32_t ahi[2][2][4], alo[2][2][4];
    {
        const int c0 = lane & 3;
#pragma unroll
        for (int m = 0; m < 2; m++) {
            const int r0 = m * 16 + (lane >> 2);
#pragma unroll
            for (int kt = 0; kt < 2; kt++) {
#pragma unroll
                for (int rg = 0; rg < 4; rg++) {
                    int row = r0 + (rg & 1) * 8;
                    int k2  = c0 + 4 * (rg >> 1) + 8 * kt;
                    float2 f = Sw2[k2 * ST2 + row];
                    uint32_t h = pack_bf16x2(f.x, f.y);
                    float he = __uint_as_float(h << 16);
                    float ho = __uint_as_float(h & 0xffff0000u);
                    ahi[m][kt][rg] = h;
                    alo[m][kt][rg] = pack_bf16x2(f.x - he, f.y - ho);
                }
            }
        }
    }

#pragma unroll 1
    for (int g = 0; g < NGEN; g++) {
        float c[2][2][4];   // [m][ntile][reg]
#pragma unroll
        for (int m = 0; m < 2; m++)
#pragma unroll
            for (int nt = 0; nt < 2; nt++)
#pragma unroll
                for (int q = 0; q < 4; q++) c[m][nt][q] = 0.0f;

#pragma unroll
        for (int kt = 0; kt < 2; kt++) {
            const int bidx = (g * 2 + kt) * 32 + lane;
            float4 bh = Bhi4[bidx];   // {nt0_b0, nt0_b1, nt1_b0, nt1_b1}
            float4 bl = Blo4[bidx];
            uint32_t bh00 = __float_as_uint(bh.x), bh01 = __float_as_uint(bh.y);
            uint32_t bh10 = __float_as_uint(bh.z), bh11 = __float_as_uint(bh.w);
            uint32_t bl00 = __float_as_uint(bl.x), bl01 = __float_as_uint(bl.y);
            uint32_t bl10 = __float_as_uint(bl.z), bl11 = __float_as_uint(bl.w);
#pragma unroll
            for (int m = 0; m < 2; m++) {
                MMA_BF16(c[m][0], ahi[m][kt], bh00, bh01);
                MMA_BF16(c[m][1], ahi[m][kt], bh10, bh11);
                MMA_BF16(c[m][0], alo[m][kt], bh00, bh01);
                MMA_BF16(c[m][1], alo[m][kt], bh10, bh11);
                MMA_BF16(c[m][0], ahi[m][kt], bl00, bl01);
                MMA_BF16(c[m][1], ahi[m][kt], bl10, bl11);
            }
        }

        // epilogue: lane's 4 outputs are contiguous cols 4q..4q+3
#pragma unroll
        for (int m = 0; m < 2; m++) {
            const int rowA = warpBase + m * 16 + (lane >> 2);
            const int rowB = rowA + 8;

            float xa0 = c[m][0][0] * c[m][0][0];
            float xa1 = c[m][0][1] * c[m][0][1];
            float xa2 = c[m][1][0] * c[m][1][0];
            float xa3 = c[m][1][1] * c[m][1][1];
            float xb0 = c[m][0][2] * c[m][0][2];
            float xb1 = c[m][0][3] * c[m][0][3];
            float xb2 = c[m][1][2] * c[m][1][2];
            float xb3 = c[m][1][3] * c[m][1][3];

            float ma = fmaxf(fmaxf(xa0, xa1), fmaxf(xa2, xa3));
            float mb = fmaxf(fmaxf(xb0, xb1), fmaxf(xb2, xb3));
            ma = fmaxf(ma, __shfl_xor_sync(0xffffffffu, ma, 1));
            mb = fmaxf(mb, __shfl_xor_sync(0xffffffffu, mb, 1));
            ma = fmaxf(ma, __shfl_xor_sync(0xffffffffu, ma, 2));
            mb = fmaxf(mb, __shfl_xor_sync(0xffffffffu, mb, 2));
            float ia = __fdividef(1.0f, ma);
            float ib = __fdividef(1.0f, mb);

            float4 va = make_float4(xa0 * ia, xa1 * ia, xa2 * ia, xa3 * ia);
            float4 vb = make_float4(xb0 * ib, xb1 * ib, xb2 * ib, xb3 * ib);
            *reinterpret_cast<float4*>(
                out + ((size_t)g * NPIX + rowA) * KEEPN + qc4) = va;
            *reinterpret_cast<float4*>(
                out + ((size_t)g * NPIX + rowB) * KEEPN + qc4) = vb;
        }
    }
}

// ---------------------------------------------------------------------------
extern "C" void kernel_launch(void* const* d_in, const int* in_sizes, int n_in,
                              void* d_out, int out_size)
{
    const float* x  = (const float*)d_in[0];   // [256,256,5]
    const float* qp = (const float*)d_in[1];   // [4,30]
    float* out = (float*)d_out;                // [4,512,512,16]

    const int smem_bytes = 2048 * 4 + 8 * 16 * ST2 * 8;   // 8KB + 36KB = 45056
    cudaFuncSetAttribute(qsrgan_mma_kernel,
                         cudaFuncAttributeMaxDynamicSharedMemorySize, smem_bytes);

    precompute_W_kernel<<<1, 128>>>(qp);
    qsrgan_mma_kernel<<<NPIX / 256, 256, smem_bytes>>>(x, out);
}

// round 16
// speedup vs baseline: 1.2326x; 1.0915x over previous
#include <cuda_runtime.h>
#include <cuda_bf16.h>
#include <cstdint>

// QSRGAN: x [256,256,5] f32, q_params [4,30] f32 -> out [4,512,512,16] f32.
//
// Two kernels, bf16 3-term-split MMA (m16n8k16), 128-thread blocks:
//  Kernel 1 (runs once, 1 block x 128 threads): evolve 32 basis columns
//    through the 6-layer RY+CZ circuit per generator (poly sincos); emit W
//    rows 0..15 as bf16 hi/lo mma B-fragments with INTERLEAVED columns.
//  Kernel 2 (2048 blocks x 128 threads, __launch_bounds__(128,7) -> 28
//    warps/SM at 72 regs): copy fragments to smem (8KB); per pixel bilinear
//    upsample + poly sincos; stage rank-1 product state as float2 pairs
//    S2[k2][pixel] (stride 36 float2). Build BOTH m16 tiles' A hi/lo
//    fragments up front; per generator load each B hi/lo float4 pair exactly
//    once; mma.sync.m16n8k16 bf16 with 3-term split AhiBhi+AloBhi+AhiBlo
//    (residual ~2^-17). Epilogue: square, quad-shuffle max, normalize;
//    interleaved B columns -> each lane's 4 outputs contiguous -> float4 STG.
//  (sum-normalization cancels: p/sum/max(p/sum) = p/max(p))
//
// B fragment layout (bf16): float4 idx (g*2+kt)*32+lane = {nt0_b0,nt0_b1,
//   nt1_b0,nt1_b1}; hi = first 256 float4, lo = next 256.
//   Column interleave: gen col i -> ntile=(i>>1)&1, n_in_tile=2*(i>>2)+(i&1).

#define DIM 32
#define KEEPN 16
#define NGEN 4
#define IW 256
#define NPIX (512*512)
#define ST2 36          // S2 row stride in float2 units
#define TPB 128         // threads per block (4 warps)

__device__ __align__(16) __nv_bfloat16 g_Bfrag[4096];   // hi[2048], lo[2048]

// sin/cos of t in [0, 0.5] via Taylor (err < 1e-9)
__device__ __forceinline__ void poly_sincos(float t, float& s, float& c) {
    float t2 = t * t;
    s = t * (1.0f + t2 * (-1.0f / 6.0f + t2 * (1.0f / 120.0f)));
    c = 1.0f + t2 * (-0.5f + t2 * (1.0f / 24.0f + t2 * (-1.0f / 720.0f)));
}

// pack two floats into bf16x2: lower half = first arg
__device__ __forceinline__ uint32_t pack_bf16x2(float even, float odd) {
    uint32_t d;
    asm("cvt.rn.bf16x2.f32 %0, %1, %2;" : "=r"(d) : "f"(odd), "f"(even));
    return d;
}

#define MMA_BF16(C, A, B0, B1)                                                 \
    asm volatile("mma.sync.aligned.m16n8k16.row.col.f32.bf16.bf16.f32 "        \
                 "{%0,%1,%2,%3}, {%4,%5,%6,%7}, {%8,%9}, {%0,%1,%2,%3};"       \
                 : "+f"((C)[0]), "+f"((C)[1]), "+f"((C)[2]), "+f"((C)[3])      \
                 : "r"((A)[0]), "r"((A)[1]), "r"((A)[2]), "r"((A)[3]),         \
                   "r"(B0), "r"(B1))

// ---------------------------------------------------------------------------
// Kernel 1: precompute circuit matrix fragments (1 block x 128 threads)
// ---------------------------------------------------------------------------
__global__ void precompute_W_kernel(const float* __restrict__ qp)
{
    const int g = threadIdx.x >> 5;    // generator
    const int j = threadIdx.x & 31;    // basis column (= GEMM k index)

    float st[DIM];
#pragma unroll
    for (int i = 0; i < DIM; i++) st[i] = (i == j) ? 1.0f : 0.0f;

#pragma unroll
    for (int d = 0; d < 6; d++) {
#pragma unroll
        for (int q = 0; q < 5; q++) {
            float s, c;
            poly_sincos(0.5f * qp[g * 30 + d * 5 + q], s, c);  // qp in [0,1)
            const int r = 1 << (4 - q);
#pragma unroll
            for (int i = 0; i < DIM; i++) {
                if ((i & r) == 0) {
                    float a0 = st[i];
                    float a1 = st[i | r];
                    st[i]     = c * a0 - s * a1;
                    st[i | r] = s * a0 + c * a1;
                }
            }
        }
#pragma unroll
        for (int i = 0; i < DIM; i++) {
            if (__popc(i & (i >> 1)) & 1) st[i] = -st[i];
        }
    }

    // Emit fragments. B[k=j][gen col i] = st[i], interleaved columns.
    const int kt  = j >> 4;
    const int kk  = j & 15;
    const int r8  = kk >> 3;
    const int ck  = (kk >> 1) & 3;
    const int par = kk & 1;
#pragma unroll
    for (int i = 0; i < KEEPN; i++) {
        float v = st[i];
        __nv_bfloat16 hi = __float2bfloat16(v);
        __nv_bfloat16 lo = __float2bfloat16(v - __bfloat162float(hi));
        int nt    = (i >> 1) & 1;
        int jn    = 2 * (i >> 2) + (i & 1);
        int lane2 = 4 * jn + ck;
        int elem  = nt * 2 + r8;
        int idx   = (((g * 2 + kt) * 32 + lane2) * 4 + elem) * 2 + par;
        g_Bfrag[idx]        = hi;
        g_Bfrag[2048 + idx] = lo;
    }
}

// ---------------------------------------------------------------------------
// Kernel 2: main kernel. 2048 blocks x 128 threads, each warp = 32 pixels.
// smem: 2048 floats B fragments (8KB) + 4 warps * 16 * ST2 float2 (18KB)
// ---------------------------------------------------------------------------
__global__ void __launch_bounds__(TPB, 7) qsrgan_mma_kernel(
    const float* __restrict__ x, float* __restrict__ out)
{
    extern __shared__ float smem[];
    float*  shB = smem;                                    // 2048 floats (8KB)
    float2* shS = reinterpret_cast<float2*>(smem + 2048);  // 4 warps * 16 * ST2

    const int tid  = threadIdx.x;
    const int lane = tid & 31;
    const int warp = tid >> 5;

    // cooperative copy of B fragments (8 KB = 512 float4, 4 per thread)
    {
        const float4* src = reinterpret_cast<const float4*>(g_Bfrag);
        float4* dst = reinterpret_cast<float4*>(shB);
#pragma unroll
        for (int t = 0; t < 4; t++) dst[tid + TPB * t] = src[tid + TPB * t];
    }

    // ---------------- Phase B: per-pixel state ----------------
    const int p  = blockIdx.x * TPB + tid;
    const int oy = p >> 9;
    const int ox = p & 511;

    float syf = oy * 0.5f - 0.25f;
    int   y0  = __float2int_rd(syf);
    float fy  = syf - (float)y0;
    int y0c = max(y0, 0);
    int y1c = min(y0 + 1, IW - 1);

    float sxf = ox * 0.5f - 0.25f;
    int   x0  = __float2int_rd(sxf);
    float fx  = sxf - (float)x0;
    int x0c = max(x0, 0);
    int x1c = min(x0 + 1, IW - 1);

    const float* p00 = x + (y0c * IW + x0c) * 5;
    const float* p01 = x + (y0c * IW + x1c) * 5;
    const float* p10 = x + (y1c * IW + x0c) * 5;
    const float* p11 = x + (y1c * IW + x1c) * 5;

    float cc[5], ss[5];
#pragma unroll
    for (int c = 0; c < 5; c++) {
        float v00 = __ldg(p00 + c);
        float v01 = __ldg(p01 + c);
        float v10 = __ldg(p10 + c);
        float v11 = __ldg(p11 + c);
        float top = v00 + fx * (v01 - v00);
        float bot = v10 + fx * (v11 - v10);
        float a   = top + fy * (bot - top);
        poly_sincos(0.5f * a, ss[c], cc[c]);     // a in [0,1) -> t in [0,0.5]
    }

    {
        float t01[4];
#pragma unroll
        for (int i = 0; i < 4; i++)
            t01[i] = ((i >> 1) ? ss[0] : cc[0]) * ((i & 1) ? ss[1] : cc[1]);
        float t012[8];
#pragma unroll
        for (int i = 0; i < 8; i++)
            t012[i] = t01[i >> 1] * ((i & 1) ? ss[2] : cc[2]);
        float t0123[16];
#pragma unroll
        for (int i = 0; i < 16; i++)
            t0123[i] = t012[i >> 1] * ((i & 1) ? ss[3] : cc[3]);

        float2* Sw2 = shS + warp * (16 * ST2) + lane;
        float c4 = cc[4], s4 = ss[4];
#pragma unroll
        for (int i = 0; i < 16; i++)
            Sw2[i * ST2] = make_float2(t0123[i] * c4, t0123[i] * s4);
    }
    __syncthreads();   // B fragments + all states visible

    // ---------------- Phase C: MMA + epilogue ------------------------------
    const float2* Sw2 = shS + warp * (16 * ST2);
    const float4* Bhi4 = reinterpret_cast<const float4*>(shB);
    const float4* Blo4 = Bhi4 + 256;
    const int warpBase = blockIdx.x * TPB + warp * 32;
    const int qc4 = 4 * (lane & 3);

    // A fragments for BOTH m-tiles (bf16 hi/lo): [m][kt][reg] = 32 regs
    uint32_t ahi[2][2][4], alo[2][2][4];
    {
        const int c0 = lane & 3;
#pragma unroll
        for (int m = 0; m < 2; m++) {
            const int r0 = m * 16 + (lane >> 2);
#pragma unroll
            for (int kt = 0; kt < 2; kt++) {
#pragma unroll
                for (int rg = 0; rg < 4; rg++) {
                    int row = r0 + (rg & 1) * 8;
                    int k2  = c0 + 4 * (rg >> 1) + 8 * kt;
                    float2 f = Sw2[k2 * ST2 + row];
                    uint32_t h = pack_bf16x2(f.x, f.y);
                    float he = __uint_as_float(h << 16);
                    float ho = __uint_as_float(h & 0xffff0000u);
                    ahi[m][kt][rg] = h;
                    alo[m][kt][rg] = pack_bf16x2(f.x - he, f.y - ho);
                }
            }
        }
    }

#pragma unroll 1
    for (int g = 0; g < NGEN; g++) {
        float c[2][2][4];   // [m][ntile][reg]
#pragma unroll
        for (int m = 0; m < 2; m++)
#pragma unroll
            for (int nt = 0; nt < 2; nt++)
#pragma unroll
                for (int q = 0; q < 4; q++) c[m][nt][q] = 0.0f;

#pragma unroll
        for (int kt = 0; kt < 2; kt++) {
            const int bidx = (g * 2 + kt) * 32 + lane;
            float4 bh = Bhi4[bidx];   // {nt0_b0, nt0_b1, nt1_b0, nt1_b1}
            float4 bl = Blo4[bidx];
            uint32_t bh00 = __float_as_uint(bh.x), bh01 = __float_as_uint(bh.y);
            uint32_t bh10 = __float_as_uint(bh.z), bh11 = __float_as_uint(bh.w);
            uint32_t bl00 = __float_as_uint(bl.x), bl01 = __float_as_uint(bl.y);
            uint32_t bl10 = __float_as_uint(bl.z), bl11 = __float_as_uint(bl.w);
#pragma unroll
            for (int m = 0; m < 2; m++) {
                MMA_BF16(c[m][0], ahi[m][kt], bh00, bh01);
                MMA_BF16(c[m][1], ahi[m][kt], bh10, bh11);
                MMA_BF16(c[m][0], alo[m][kt], bh00, bh01);
                MMA_BF16(c[m][1], alo[m][kt], bh10, bh11);
                MMA_BF16(c[m][0], ahi[m][kt], bl00, bl01);
                MMA_BF16(c[m][1], ahi[m][kt], bl10, bl11);
            }
        }

        // epilogue: lane's 4 outputs are contiguous cols 4q..4q+3
#pragma unroll
        for (int m = 0; m < 2; m++) {
            const int rowA = warpBase + m * 16 + (lane >> 2);
            const int rowB = rowA + 8;

            float xa0 = c[m][0][0] * c[m][0][0];
            float xa1 = c[m][0][1] * c[m][0][1];
            float xa2 = c[m][1][0] * c[m][1][0];
            float xa3 = c[m][1][1] * c[m][1][1];
            float xb0 = c[m][0][2] * c[m][0][2];
            float xb1 = c[m][0][3] * c[m][0][3];
            float xb2 = c[m][1][2] * c[m][1][2];
            float xb3 = c[m][1][3] * c[m][1][3];

            float ma = fmaxf(fmaxf(xa0, xa1), fmaxf(xa2, xa3));
            float mb = fmaxf(fmaxf(xb0, xb1), fmaxf(xb2, xb3));
            ma = fmaxf(ma, __shfl_xor_sync(0xffffffffu, ma, 1));
            mb = fmaxf(mb, __shfl_xor_sync(0xffffffffu, mb, 1));
            ma = fmaxf(ma, __shfl_xor_sync(0xffffffffu, ma, 2));
            mb = fmaxf(mb, __shfl_xor_sync(0xffffffffu, mb, 2));
            float ia = __fdividef(1.0f, ma);
            float ib = __fdividef(1.0f, mb);

            float4 va = make_float4(xa0 * ia, xa1 * ia, xa2 * ia, xa3 * ia);
            float4 vb = make_float4(xb0 * ib, xb1 * ib, xb2 * ib, xb3 * ib);
            *reinterpret_cast<float4*>(
                out + ((size_t)g * NPIX + rowA) * KEEPN + qc4) = va;
            *reinterpret_cast<float4*>(
                out + ((size_t)g * NPIX + rowB) * KEEPN + qc4) = vb;
        }
    }
}

// ---------------------------------------------------------------------------
extern "C" void kernel_launch(void* const* d_in, const int* in_sizes, int n_in,
                              void* d_out, int out_size)
{
    const float* x  = (const float*)d_in[0];   // [256,256,5]
    const float* qp = (const float*)d_in[1];   // [4,30]
    float* out = (float*)d_out;                // [4,512,512,16]

    const int smem_bytes = 2048 * 4 + 4 * 16 * ST2 * 8;   // 8KB + 18KB = 26624
    cudaFuncSetAttribute(qsrgan_mma_kernel,
                         cudaFuncAttributeMaxDynamicSharedMemorySize, smem_bytes);

    precompute_W_kernel<<<1, 128>>>(qp);
    qsrgan_mma_kernel<<<NPIX / TPB, TPB, smem_bytes>>>(x, out);
}